// round 16
// baseline (speedup 1.0000x reference)
#include <cuda_runtime.h>
#include <cuda_bf16.h>
#include <math.h>
#include <stdint.h>

// Problem constants (fixed: B=8, L=1024, E=8, D=512, 2 layers)
#define TOKENS 8192
#define DIM    512
#define NEXP   8
#define MAXE   64
#define LN_EPS 1e-5f
#define NSPLIT 4
#define MEGA_BLOCKS 512
#define FUS_BLOCKS  384   // blocks 0..383: fusion chain
                          // blocks 384..511: expert reduce (overlapped)

// ---------------- scratch (device globals) ---------------------------------
__device__ __nv_bfloat16  g_mh[TOKENS * DIM];        // m hi
__device__ __nv_bfloat16  g_ml[TOKENS * DIM];        // m lo
__device__ __nv_bfloat16  g_wh[DIM * DIM];           // Wf hi
__device__ __nv_bfloat16  g_wl[DIM * DIM];           // Wf lo
__device__ float          g_T1[DIM * DIM];           // W1 @ W0
__device__ float          g_part[NSPLIT * DIM * DIM];
__device__ float          g_part2[NSPLIT * DIM * DIM];
__device__ float          g_bf[DIM];
__device__ float          g_tb[DIM];
__device__ float          g_v[NEXP];
__device__ float          g_s;
__device__ float          g_lnsum[TOKENS];           // cross-CTA LN partials
__device__ float          g_lnsq[TOKENS];
__device__ int            g_lncnt[TOKENS / 64];
__device__ int            g_bar[4];                  // [0..2] barriers, [3] v-ready

// ---------------- common PTX helpers ----------------------------------------
__device__ __forceinline__ void cp_async16(uint32_t saddr, const void* gptr) {
    asm volatile("cp.async.cg.shared.global [%0], [%1], 16;\n"
                 :: "r"(saddr), "l"(gptr));
}
__device__ __forceinline__ void cp_commit() {
    asm volatile("cp.async.commit_group;\n");
}
template <int N>
__device__ __forceinline__ void cp_wait() {
    asm volatile("cp.async.wait_group %0;\n" :: "n"(N));
}
__device__ __forceinline__ void ldsm_x4(uint32_t* r, uint32_t addr) {
    asm volatile(
        "ldmatrix.sync.aligned.m8n8.x4.shared.b16 {%0,%1,%2,%3}, [%4];"
        : "=r"(r[0]), "=r"(r[1]), "=r"(r[2]), "=r"(r[3]) : "r"(addr));
}
__device__ __forceinline__ void mma_bf16(float* d, const uint32_t* a,
                                         uint32_t b0, uint32_t b1) {
    asm volatile(
        "mma.sync.aligned.m16n8k16.row.col.f32.bf16.bf16.f32 "
        "{%0,%1,%2,%3}, {%4,%5,%6,%7}, {%8,%9}, {%0,%1,%2,%3};"
        : "+f"(d[0]), "+f"(d[1]), "+f"(d[2]), "+f"(d[3])
        : "r"(a[0]), "r"(a[1]), "r"(a[2]), "r"(a[3]), "r"(b0), "r"(b1));
}
__device__ __forceinline__ uint32_t smem_u32(const void* p) {
    uint32_t a;
    asm("{ .reg .u64 t; cvta.to.shared.u64 t, %1; cvt.u32.u64 %0, t; }"
        : "=r"(a) : "l"(p));
    return a;
}
__device__ __forceinline__ void split_bf16(float x, __nv_bfloat16& h,
                                           __nv_bfloat16& l) {
    h = __float2bfloat16(x);
    l = __float2bfloat16(x - __bfloat162float(h));
}
__device__ __forceinline__ float gelu_exact(float x) {
    return 0.5f * x * (1.0f + erff(x * 0.70710678118654752f));
}

// ---------------- mega kernel (unchanged from R14 best) ----------------------
__device__ __forceinline__ void gbar(int k) {
    __syncthreads();
    __threadfence();
    if (threadIdx.x == 0) {
        atomicAdd(&g_bar[k], 1);
        volatile int* c = (volatile int*)&g_bar[k];
        while (*c < FUS_BLOCKS) {}
    }
    __syncthreads();
    __threadfence();
}

__device__ void sk_compute(const float* __restrict__ A,
                           const float* __restrict__ B,
                           float* __restrict__ out,
                           int bm, int bn, int kz,
                           float (*As)[68], float (*Bs)[68]) {
    const int tid = threadIdx.x;
    const int tx = tid & 15, ty = tid >> 4;

    float acc[4][4];
#pragma unroll
    for (int i = 0; i < 4; i++)
#pragma unroll
        for (int j = 0; j < 4; j++) acc[i][j] = 0.0f;

    for (int k0 = kz; k0 < kz + 128; k0 += 16) {
        {
            int row = tid >> 2, c4 = tid & 3;
            float4 v = *reinterpret_cast<const float4*>(
                &A[(size_t)(bm + row) * DIM + k0 + c4 * 4]);
            As[c4 * 4 + 0][row] = v.x; As[c4 * 4 + 1][row] = v.y;
            As[c4 * 4 + 2][row] = v.z; As[c4 * 4 + 3][row] = v.w;
        }
        {
            int krow = tid >> 4, c4 = tid & 15;
            float4 v = *reinterpret_cast<const float4*>(
                &B[(size_t)(k0 + krow) * DIM + bn + c4 * 4]);
            *reinterpret_cast<float4*>(&Bs[krow][c4 * 4]) = v;
        }
        __syncthreads();
#pragma unroll
        for (int k = 0; k < 16; k++) {
            float ra[4], rb[4];
#pragma unroll
            for (int i = 0; i < 4; i++) ra[i] = As[k][ty * 4 + i];
#pragma unroll
            for (int j = 0; j < 4; j++) rb[j] = Bs[k][tx * 4 + j];
#pragma unroll
            for (int i = 0; i < 4; i++)
#pragma unroll
                for (int j = 0; j < 4; j++) acc[i][j] += ra[i] * rb[j];
        }
        __syncthreads();
    }
#pragma unroll
    for (int i = 0; i < 4; i++) {
        int row = bm + ty * 4 + i;
        float4 v = make_float4(acc[i][0], acc[i][1], acc[i][2], acc[i][3]);
        *reinterpret_cast<float4*>(&out[(size_t)row * DIM + bn + tx * 4]) = v;
    }
}

__device__ void structure_body(const int* __restrict__ nodes,
                               const int* __restrict__ edges, int nn) {
    __shared__ float deg[NEXP];
    __shared__ float edeg[MAXE];
    __shared__ int   Hc[NEXP][MAXE];
    __shared__ float P[NEXP][NEXP];
    __shared__ float u[NEXP];
    const int t = threadIdx.x;  // 256

    if (t < NEXP) deg[t] = 0.0f;
    if (t < MAXE) edeg[t] = 0.0f;
    for (int i = t; i < NEXP * MAXE; i += 256) (&Hc[0][0])[i] = 0;
    __syncthreads();

    int ne = nn / 2;
    if (ne > MAXE) ne = MAXE;
    for (int k = t; k < nn; k += 256) {
        int i = nodes[k], e = edges[k];
        if (i < 0 || i >= NEXP || e < 0 || e >= ne) continue;
        atomicAdd(&Hc[i][e], 1);
        atomicAdd(&deg[i], 1.0f);
        atomicAdd(&edeg[e], 1.0f);
    }
    __syncthreads();

    if (t < NEXP * NEXP) {
        int i = t >> 3, j = t & 7;
        float acc = 0.0f;
        for (int e = 0; e < ne; e++) {
            float binv = edeg[e] > 0.0f ? 1.0f / edeg[e] : 0.0f;
            acc += (float)Hc[i][e] * binv * (float)Hc[j][e];
        }
        float dinv = deg[i] > 0.0f ? 1.0f / deg[i] : 0.0f;
        P[i][j] = dinv * acc;
    }
    __syncthreads();
    if (t < NEXP) {
        float a = 0.0f;
        for (int i = 0; i < NEXP; i++) a += P[i][t];
        u[t] = a / (float)NEXP;
    }
    __syncthreads();
    if (t < NEXP) {
        float a = 0.0f;
        for (int i = 0; i < NEXP; i++) a += u[i] * P[i][t];
        g_v[t] = a;
    }
    if (t == 0) {
        float s = 0.0f;
        for (int i = 0; i < NEXP; i++) s += u[i];
        g_s = s;
    }
    __syncthreads();
}

__global__ __launch_bounds__(256, 4) void mega_kernel(
    const int* __restrict__ nodes, const int* __restrict__ edges, int nn,
    const float* __restrict__ W1, const float* __restrict__ W0,
    const float* __restrict__ Wc, const float* __restrict__ b0,
    const float* __restrict__ b1, const float* __restrict__ cb,
    const float* __restrict__ x) {
    const int bid = blockIdx.x;
    const int tid = threadIdx.x;

    if (bid >= FUS_BLOCKS) {
        if (tid == 0) {
            volatile int* f = (volatile int*)&g_bar[3];
            while (*f == 0) {}
        }
        __syncthreads();
        __threadfence();

        float v[NEXP];
#pragma unroll
        for (int e = 0; e < NEXP; e++) v[e] = __ldcg(&g_v[e]);

        const int rb = bid - FUS_BLOCKS;  // 0..127
        __nv_bfloat162* mh = reinterpret_cast<__nv_bfloat162*>(g_mh);
        __nv_bfloat162* ml = reinterpret_cast<__nv_bfloat162*>(g_ml);
#pragma unroll 1
        for (int it = 0; it < 32; it++) {
            int idx = rb * 8192 + it * 256 + tid;  // float4 index
            int n  = idx >> 7;
            int d4 = idx & 127;
            const float4* base =
                reinterpret_cast<const float4*>(x) + (size_t)n * NEXP * 128 + d4;
            float4 acc = make_float4(0.f, 0.f, 0.f, 0.f);
#pragma unroll
            for (int e = 0; e < NEXP; e++) {
                float4 q = base[(size_t)e * 128];
                acc.x += v[e] * q.x; acc.y += v[e] * q.y;
                acc.z += v[e] * q.z; acc.w += v[e] * q.w;
            }
            __nv_bfloat16 h0, h1, h2, h3, l0, l1, l2, l3;
            split_bf16(acc.x, h0, l0); split_bf16(acc.y, h1, l1);
            split_bf16(acc.z, h2, l2); split_bf16(acc.w, h3, l3);
            mh[idx * 2 + 0] = __halves2bfloat162(h0, h1);
            mh[idx * 2 + 1] = __halves2bfloat162(h2, h3);
            ml[idx * 2 + 0] = __halves2bfloat162(l0, l1);
            ml[idx * 2 + 1] = __halves2bfloat162(l2, l3);
        }
        return;
    }

    __shared__ float As[16][68];
    __shared__ float Bs[16][68];
    __shared__ float gred[8];
    const int z = bid >> 6, t6 = bid & 63;
    const int bm = (t6 >> 3) * 64, bn = (t6 & 7) * 64, kz = z * 128;

    if (bid == 0) {
        structure_body(nodes, edges, nn);
        if (tid == 0) {
            __threadfence();
            atomicExch(&g_bar[3], 1);
        }
    }

    if (bid < 256) {
        sk_compute(W1, W0, g_part + (size_t)z * DIM * DIM, bm, bn, kz, As, Bs);
    } else {
        int i = (bid - 256) * 256 + tid;
        if (i < TOKENS) { g_lnsum[i] = 0.0f; g_lnsq[i] = 0.0f; }
        if (i >= TOKENS && i < TOKENS + TOKENS / 64)
            g_lncnt[i - TOKENS] = 0;
    }

    gbar(0);

    if (bid < 64) {
        const float4* p = reinterpret_cast<const float4*>(g_part);
#pragma unroll
        for (int k = 0; k < 4; k++) {
            int i = bid * 1024 + k * 256 + tid;
            float4 s = make_float4(0.f, 0.f, 0.f, 0.f);
#pragma unroll
            for (int j = 0; j < NSPLIT; j++) {
                float4 a = p[i + j * 65536];
                s.x += a.x; s.y += a.y; s.z += a.z; s.w += a.w;
            }
            reinterpret_cast<float4*>(g_T1)[i] = s;
        }
    } else if (bid < 320) {
        const int half = tid >> 7, lt = tid & 127;
        const int r = (bid - 64) * 2 + half;
        float4 wv = reinterpret_cast<const float4*>(W1 + (size_t)r * DIM)[lt];
        float4 bv = reinterpret_cast<const float4*>(b0)[lt];
        float a = wv.x * bv.x + wv.y * bv.y + wv.z * bv.z + wv.w * bv.w;
        for (int o = 16; o; o >>= 1) a += __shfl_xor_sync(0xffffffffu, a, o);
        if ((tid & 31) == 0) gred[tid >> 5] = a;
        __syncthreads();
        if (lt == 0)
            g_tb[r] = gred[half * 4 + 0] + gred[half * 4 + 1] +
                      gred[half * 4 + 2] + gred[half * 4 + 3];
    }

    gbar(1);

    if (bid < 256)
        sk_compute(Wc, g_T1, g_part2 + (size_t)z * DIM * DIM, bm, bn, kz,
                   As, Bs);

    gbar(2);

    if (bid < 64) {
        const float4* p = reinterpret_cast<const float4*>(g_part2);
        __nv_bfloat162* wh = reinterpret_cast<__nv_bfloat162*>(g_wh);
        __nv_bfloat162* wl = reinterpret_cast<__nv_bfloat162*>(g_wl);
#pragma unroll
        for (int k = 0; k < 4; k++) {
            int i = bid * 1024 + k * 256 + tid;
            float4 s = make_float4(0.f, 0.f, 0.f, 0.f);
#pragma unroll
            for (int j = 0; j < NSPLIT; j++) {
                float4 a = p[i + j * 65536];
                s.x += a.x; s.y += a.y; s.z += a.z; s.w += a.w;
            }
            __nv_bfloat16 h0, h1, h2, h3, l0, l1, l2, l3;
            split_bf16(s.x, h0, l0); split_bf16(s.y, h1, l1);
            split_bf16(s.z, h2, l2); split_bf16(s.w, h3, l3);
            wh[i * 2 + 0] = __halves2bfloat162(h0, h1);
            wh[i * 2 + 1] = __halves2bfloat162(h2, h3);
            wl[i * 2 + 0] = __halves2bfloat162(l0, l1);
            wl[i * 2 + 1] = __halves2bfloat162(l2, l3);
        }
    } else if (bid < 320) {
        const int half = tid >> 7, lt = tid & 127;
        const int r = (bid - 64) * 2 + half;
        const float s = g_s;
        float4 wv = reinterpret_cast<const float4*>(Wc + (size_t)r * DIM)[lt];
        float4 bv = reinterpret_cast<const float4*>(b1)[lt];
        float a = wv.x * (s * g_tb[lt * 4 + 0] + bv.x) +
                  wv.y * (s * g_tb[lt * 4 + 1] + bv.y) +
                  wv.z * (s * g_tb[lt * 4 + 2] + bv.z) +
                  wv.w * (s * g_tb[lt * 4 + 3] + bv.w);
        for (int o = 16; o; o >>= 1) a += __shfl_xor_sync(0xffffffffu, a, o);
        __syncthreads();
        if ((tid & 31) == 0) gred[tid >> 5] = a;
        __syncthreads();
        if (lt == 0)
            g_bf[r] = gred[half * 4 + 0] + gred[half * 4 + 1] +
                      gred[half * 4 + 2] + gred[half * 4 + 3] + cb[r];
    }
}

// ---------------- fused HMMA GEMM + bias + GELU + cross-CTA LayerNorm -------
// Re-tiled: CTA 128(M)x128(N), grid (4,64); 8 warps as 4(M)x2(N), warp tile
// 32x64 (inner loop identical to R14). ldsm per k16-step: 20 -> 12.
// LN reduction across the 4 CTAs of a 128-row block (all 256 CTAs resident).
#define BK   32
#define BKP  40
#define A_T_E (128 * BKP)
#define B_T_E (128 * BKP)
#define OFF_AH 0
#define OFF_AL (A_T_E * 2)            // 10240
#define OFF_BH (2 * A_T_E * 2)        // 20480
#define OFF_BL (OFF_BH + B_T_E * 2)   // 30720
#define STG_B  (OFF_BL + B_T_E * 2)   // 40960 B per stage
#define GEMM_SMEM_B (2 * STG_B)       // 81920 B

__global__ __launch_bounds__(256, 2) void gemm_ln(
    const float* __restrict__ gamma, const float* __restrict__ beta,
    float* __restrict__ out) {
    extern __shared__ __nv_bfloat16 smem[];
    __shared__ float red[128][2][2];  // [row][n-warp][sum,sq]
    const uint32_t sb = smem_u32(smem);
    const int tid  = threadIdx.x;
    const int wid  = tid >> 5;
    const int lane = tid & 31;
    const int bm = blockIdx.y * 128;
    const int bn = blockIdx.x * 128;
    const int wm = (wid & 3) * 32;   // warp m offset (0,32,64,96)
    const int wn = (wid >> 2) * 64;  // warp n offset (0 or 64)

    // reset mega's spin barriers for the next replay
    if (blockIdx.x == 0 && blockIdx.y == 0 && tid < 4) g_bar[tid] = 0;

    float acc[2][8][4];
#pragma unroll
    for (int i = 0; i < 2; i++)
#pragma unroll
        for (int j = 0; j < 8; j++)
#pragma unroll
            for (int r = 0; r < 4; r++) acc[i][j][r] = 0.0f;

    const int lrow = (lane & 7) + ((lane >> 3) & 1) * 8;
    const int lcol = (lane >> 4) * 8;
    const uint32_t a_eoff = (uint32_t)(((wm + lrow) * BKP + lcol) * 2);
    const uint32_t b_eoff = (uint32_t)(((wn + lrow) * BKP + lcol) * 2);

    const int r_ld = tid >> 2;   // 0..63 (rows r_ld and r_ld+64)
    const int u_ld = tid & 3;

    // hoisted global source pointers (advance by BK per stage)
    const __nv_bfloat16* pA[2][2];  // [h/l][row half]
    const __nv_bfloat16* pBp[2][2];
    pA[0][0] = g_mh + (size_t)(bm + r_ld) * DIM + u_ld * 8;
    pA[0][1] = g_mh + (size_t)(bm + r_ld + 64) * DIM + u_ld * 8;
    pA[1][0] = g_ml + (size_t)(bm + r_ld) * DIM + u_ld * 8;
    pA[1][1] = g_ml + (size_t)(bm + r_ld + 64) * DIM + u_ld * 8;
    pBp[0][0] = g_wh + (size_t)(bn + r_ld) * DIM + u_ld * 8;
    pBp[0][1] = g_wh + (size_t)(bn + r_ld + 64) * DIM + u_ld * 8;
    pBp[1][0] = g_wl + (size_t)(bn + r_ld) * DIM + u_ld * 8;
    pBp[1][1] = g_wl + (size_t)(bn + r_ld + 64) * DIM + u_ld * 8;

    const uint32_t doff0 = (uint32_t)((r_ld * BKP + u_ld * 8) * 2);
    const uint32_t doff1 = (uint32_t)(((r_ld + 64) * BKP + u_ld * 8) * 2);

    uint32_t sAh[2], sAl[2], sBh[2], sBl[2];
#pragma unroll
    for (int b = 0; b < 2; b++) {
        const uint32_t stg = sb + (uint32_t)(b * STG_B);
        sAh[b] = stg + OFF_AH + a_eoff;
        sAl[b] = stg + OFF_AL + a_eoff;
        sBh[b] = stg + OFF_BH + b_eoff;
        sBl[b] = stg + OFF_BL + b_eoff;
    }

    auto issue_stage = [&](int buf) {
        const uint32_t stg = sb + (uint32_t)(buf * STG_B);
        cp_async16(stg + OFF_AH + doff0, pA[0][0]);
        cp_async16(stg + OFF_AH + doff1, pA[0][1]);
        cp_async16(stg + OFF_AL + doff0, pA[1][0]);
        cp_async16(stg + OFF_AL + doff1, pA[1][1]);
        cp_async16(stg + OFF_BH + doff0, pBp[0][0]);
        cp_async16(stg + OFF_BH + doff1, pBp[0][1]);
        cp_async16(stg + OFF_BL + doff0, pBp[1][0]);
        cp_async16(stg + OFF_BL + doff1, pBp[1][1]);
#pragma unroll
        for (int i = 0; i < 2; i++)
#pragma unroll
            for (int j = 0; j < 2; j++) { pA[i][j] += BK; pBp[i][j] += BK; }
    };

    issue_stage(0);
    cp_commit();

    const int NSTG = DIM / BK;  // 16
    for (int c = 0; c < NSTG; c++) {
        const int buf = c & 1;
        if (c + 1 < NSTG) { issue_stage((c + 1) & 1); cp_commit(); }
        if (c + 1 < NSTG) cp_wait<1>(); else cp_wait<0>();
        __syncthreads();

        const uint32_t pAhS = sAh[buf];
        const uint32_t pAlS = sAl[buf];
        const uint32_t pBhS = sBh[buf];
        const uint32_t pBlS = sBl[buf];

#pragma unroll
        for (int kk = 0; kk < BK; kk += 16) {
            const uint32_t ko = (uint32_t)(kk * 2);
            uint32_t Ahf[2][4], Alf[2][4];
#pragma unroll
            for (int mi = 0; mi < 2; mi++) {
                const uint32_t o = (uint32_t)(mi * 16 * BKP * 2) + ko;
                ldsm_x4(Ahf[mi], pAhS + o);
                ldsm_x4(Alf[mi], pAlS + o);
            }
            uint32_t Bh[2][4], Bl[2][4];
            ldsm_x4(Bh[0], pBhS + ko);
            ldsm_x4(Bl[0], pBlS + ko);
#pragma unroll
            for (int g = 0; g < 4; g++) {
                const int cur = g & 1;
                if (g < 3) {
                    const uint32_t o = (uint32_t)((g + 1) * 16 * BKP * 2) + ko;
                    ldsm_x4(Bh[cur ^ 1], pBhS + o);
                    ldsm_x4(Bl[cur ^ 1], pBlS + o);
                }
#pragma unroll
                for (int hf = 0; hf < 2; hf++) {
                    const int n8 = g * 2 + hf;
                    const uint32_t bh0 = Bh[cur][hf], bh1 = Bh[cur][hf + 2];
                    const uint32_t bl0 = Bl[cur][hf], bl1 = Bl[cur][hf + 2];
#pragma unroll
                    for (int mi = 0; mi < 2; mi++) {
                        mma_bf16(acc[mi][n8], Ahf[mi], bh0, bh1);
                        mma_bf16(acc[mi][n8], Ahf[mi], bl0, bl1);
                        mma_bf16(acc[mi][n8], Alf[mi], bh0, bh1);
                    }
                }
            }
        }
        __syncthreads();
    }

    // ---------------- epilogue: bias + GELU + cross-CTA LayerNorm -----------
    const int q = lane >> 2;
    float sm_[2][2] = {{0.f, 0.f}, {0.f, 0.f}};
    float sq_[2][2] = {{0.f, 0.f}, {0.f, 0.f}};
#pragma unroll
    for (int mi = 0; mi < 2; mi++)
#pragma unroll
        for (int n8 = 0; n8 < 8; n8++) {
            const int col = bn + wn + n8 * 8 + (lane & 3) * 2;
            const float2 bv = *reinterpret_cast<const float2*>(&g_bf[col]);
            float g0 = gelu_exact(acc[mi][n8][0] + bv.x);
            float g1 = gelu_exact(acc[mi][n8][1] + bv.y);
            float g2 = gelu_exact(acc[mi][n8][2] + bv.x);
            float g3 = gelu_exact(acc[mi][n8][3] + bv.y);
            acc[mi][n8][0] = g0; acc[mi][n8][1] = g1;
            acc[mi][n8][2] = g2; acc[mi][n8][3] = g3;
            sm_[mi][0] += g0 + g1; sq_[mi][0] += g0 * g0 + g1 * g1;
            sm_[mi][1] += g2 + g3; sq_[mi][1] += g2 * g2 + g3 * g3;
        }
#pragma unroll
    for (int o = 1; o <= 2; o <<= 1) {
#pragma unroll
        for (int mi = 0; mi < 2; mi++)
#pragma unroll
            for (int h = 0; h < 2; h++) {
                sm_[mi][h] += __shfl_xor_sync(0xffffffffu, sm_[mi][h], o);
                sq_[mi][h] += __shfl_xor_sync(0xffffffffu, sq_[mi][h], o);
            }
    }
    const int nw = wid >> 2;  // n-warp index (0 or 1)
    if ((lane & 3) == 0) {
#pragma unroll
        for (int mi = 0; mi < 2; mi++)
#pragma unroll
            for (int h = 0; h < 2; h++) {
                red[wm + mi * 16 + q + h * 8][nw][0] = sm_[mi][h];
                red[wm + mi * 16 + q + h * 8][nw][1] = sq_[mi][h];
            }
    }
    __syncthreads();

    // per-row partials -> global atomics (threads 0..127 own one row each)
    if (tid < 128) {
        float s  = red[tid][0][0] + red[tid][1][0];
        float qq = red[tid][0][1] + red[tid][1][1];
        atomicAdd(&g_lnsum[bm + tid], s);
        atomicAdd(&g_lnsq[bm + tid], qq);
        __threadfence();
    }
    __syncthreads();
    if (tid == 0) {
        atomicAdd(&g_lncnt[blockIdx.y], 1);
        volatile int* cnt = (volatile int*)&g_lncnt[blockIdx.y];
        while (*cnt < 4) {}
    }
    __syncthreads();
    __threadfence();

    const float inv_d = 1.0f / (float)DIM;
    float mu[2][2], iv[2][2];
#pragma unroll
    for (int mi = 0; mi < 2; mi++)
#pragma unroll
        for (int h = 0; h < 2; h++) {
            const int row = bm + wm + mi * 16 + q + h * 8;
            float s  = __ldcg(&g_lnsum[row]);
            float qq = __ldcg(&g_lnsq[row]);
            float m = s * inv_d;
            mu[mi][h] = m;
            iv[mi][h] = rsqrtf(qq * inv_d - m * m + LN_EPS);
        }

#pragma unroll
    for (int mi = 0; mi < 2; mi++) {
        const int r0 = bm + wm + mi * 16 + q;
        const int r1 = r0 + 8;
#pragma unroll
        for (int n8 = 0; n8 < 8; n8++) {
            const int col = bn + wn + n8 * 8 + (lane & 3) * 2;
            const float2 ga = *reinterpret_cast<const float2*>(&gamma[col]);
            const float2 be = *reinterpret_cast<const float2*>(&beta[col]);
            float2 o0, o1;
            o0.x = (acc[mi][n8][0] - mu[mi][0]) * iv[mi][0] * ga.x + be.x;
            o0.y = (acc[mi][n8][1] - mu[mi][0]) * iv[mi][0] * ga.y + be.y;
            o1.x = (acc[mi][n8][2] - mu[mi][1]) * iv[mi][1] * ga.x + be.x;
            o1.y = (acc[mi][n8][3] - mu[mi][1]) * iv[mi][1] * ga.y + be.y;
            *reinterpret_cast<float2*>(&out[(size_t)r0 * DIM + col]) = o0;
            *reinterpret_cast<float2*>(&out[(size_t)r1 * DIM + col]) = o1;
        }
    }
}

// ---------------- launcher ---------------------------------------------------
extern "C" void kernel_launch(void* const* d_in, const int* in_sizes, int n_in,
                              void* d_out, int out_size) {
    const float* x     = (const float*)d_in[0];
    const float* hw    = (const float*)d_in[1];
    const float* hb    = (const float*)d_in[2];
    const float* cw    = (const float*)d_in[3];
    const float* cbias = (const float*)d_in[4];
    const float* lg    = (const float*)d_in[5];
    const float* lb    = (const float*)d_in[6];
    const int*   nodes = (const int*)d_in[7];
    const int*   edges = (const int*)d_in[8];
    const int    nn    = in_sizes[7];
    float*       out   = (float*)d_out;

    const float* W0 = hw;
    const float* W1 = hw + DIM * DIM;
    const float* b0 = hb;
    const float* b1 = hb + DIM;

    cudaFuncSetAttribute(gemm_ln, cudaFuncAttributeMaxDynamicSharedMemorySize,
                         GEMM_SMEM_B);

    // 1) mega: fusion chain (blocks 0-383, also zeroes LN buffers)
    //          || expert reduce (blocks 384-511)
    mega_kernel<<<MEGA_BLOCKS, 256>>>(nodes, edges, nn, W1, W0, cw, b0, b1,
                                      cbias, x);

    // 2) main HMMA GEMM + bias + GELU + cross-CTA LayerNorm -> out
    //    (also zeroes g_bar for the next replay's mega)
    {
        dim3 grid(4, TOKENS / 128);
        gemm_ln<<<grid, 256, GEMM_SMEM_B>>>(lg, lb, out);
    }
}

// round 17
// speedup vs baseline: 1.0055x; 1.0055x over previous
#include <cuda_runtime.h>
#include <cuda_bf16.h>
#include <math.h>
#include <stdint.h>

// Problem constants (fixed: B=8, L=1024, E=8, D=512, 2 layers)
#define TOKENS 8192
#define DIM    512
#define NEXP   8
#define MAXE   64
#define LN_EPS 1e-5f
#define NSPLIT 4
#define MEGA_BLOCKS 512
#define FUS_BLOCKS  384   // blocks 0..383: fusion chain
                          // blocks 384..511: expert reduce (overlapped)

// ---------------- scratch (device globals) ---------------------------------
__device__ __nv_bfloat16  g_mh[TOKENS * DIM];        // m hi
__device__ __nv_bfloat16  g_ml[TOKENS * DIM];        // m lo
__device__ __nv_bfloat16  g_wh[DIM * DIM];           // Wf hi
__device__ __nv_bfloat16  g_wl[DIM * DIM];           // Wf lo
__device__ float          g_T1[DIM * DIM];           // W1 @ W0
__device__ float          g_part[NSPLIT * DIM * DIM];
__device__ float          g_part2[NSPLIT * DIM * DIM];
__device__ float          g_bf[DIM];
__device__ float          g_tb[DIM];
__device__ float          g_v[NEXP];
__device__ float          g_s;
__device__ float          g_lnsum[TOKENS];           // cross-CTA LN partials
__device__ float          g_lnsq[TOKENS];
__device__ int            g_lncnt[TOKENS / 64];
__device__ int            g_bar[4];                  // [0..2] barriers, [3] v-ready

// ---------------- common PTX helpers ----------------------------------------
__device__ __forceinline__ void cp_async16(uint32_t saddr, const void* gptr) {
    asm volatile("cp.async.cg.shared.global [%0], [%1], 16;\n"
                 :: "r"(saddr), "l"(gptr));
}
__device__ __forceinline__ void cp_commit() {
    asm volatile("cp.async.commit_group;\n");
}
template <int N>
__device__ __forceinline__ void cp_wait() {
    asm volatile("cp.async.wait_group %0;\n" :: "n"(N));
}
__device__ __forceinline__ void ldsm_x4(uint32_t* r, uint32_t addr) {
    asm volatile(
        "ldmatrix.sync.aligned.m8n8.x4.shared.b16 {%0,%1,%2,%3}, [%4];"
        : "=r"(r[0]), "=r"(r[1]), "=r"(r[2]), "=r"(r[3]) : "r"(addr));
}
__device__ __forceinline__ void mma_bf16(float* d, const uint32_t* a,
                                         uint32_t b0, uint32_t b1) {
    asm volatile(
        "mma.sync.aligned.m16n8k16.row.col.f32.bf16.bf16.f32 "
        "{%0,%1,%2,%3}, {%4,%5,%6,%7}, {%8,%9}, {%0,%1,%2,%3};"
        : "+f"(d[0]), "+f"(d[1]), "+f"(d[2]), "+f"(d[3])
        : "r"(a[0]), "r"(a[1]), "r"(a[2]), "r"(a[3]), "r"(b0), "r"(b1));
}
__device__ __forceinline__ uint32_t smem_u32(const void* p) {
    uint32_t a;
    asm("{ .reg .u64 t; cvta.to.shared.u64 t, %1; cvt.u32.u64 %0, t; }"
        : "=r"(a) : "l"(p));
    return a;
}
__device__ __forceinline__ void split_bf16(float x, __nv_bfloat16& h,
                                           __nv_bfloat16& l) {
    h = __float2bfloat16(x);
    l = __float2bfloat16(x - __bfloat162float(h));
}
__device__ __forceinline__ float gelu_exact(float x) {
    return 0.5f * x * (1.0f + erff(x * 0.70710678118654752f));
}

// ---------------- mega kernel (unchanged from R14 best) ----------------------
__device__ __forceinline__ void gbar(int k) {
    __syncthreads();
    __threadfence();
    if (threadIdx.x == 0) {
        atomicAdd(&g_bar[k], 1);
        volatile int* c = (volatile int*)&g_bar[k];
        while (*c < FUS_BLOCKS) {}
    }
    __syncthreads();
    __threadfence();
}

__device__ void sk_compute(const float* __restrict__ A,
                           const float* __restrict__ B,
                           float* __restrict__ out,
                           int bm, int bn, int kz,
                           float (*As)[68], float (*Bs)[68]) {
    const int tid = threadIdx.x;
    const int tx = tid & 15, ty = tid >> 4;

    float acc[4][4];
#pragma unroll
    for (int i = 0; i < 4; i++)
#pragma unroll
        for (int j = 0; j < 4; j++) acc[i][j] = 0.0f;

    for (int k0 = kz; k0 < kz + 128; k0 += 16) {
        {
            int row = tid >> 2, c4 = tid & 3;
            float4 v = *reinterpret_cast<const float4*>(
                &A[(size_t)(bm + row) * DIM + k0 + c4 * 4]);
            As[c4 * 4 + 0][row] = v.x; As[c4 * 4 + 1][row] = v.y;
            As[c4 * 4 + 2][row] = v.z; As[c4 * 4 + 3][row] = v.w;
        }
        {
            int krow = tid >> 4, c4 = tid & 15;
            float4 v = *reinterpret_cast<const float4*>(
                &B[(size_t)(k0 + krow) * DIM + bn + c4 * 4]);
            *reinterpret_cast<float4*>(&Bs[krow][c4 * 4]) = v;
        }
        __syncthreads();
#pragma unroll
        for (int k = 0; k < 16; k++) {
            float ra[4], rb[4];
#pragma unroll
            for (int i = 0; i < 4; i++) ra[i] = As[k][ty * 4 + i];
#pragma unroll
            for (int j = 0; j < 4; j++) rb[j] = Bs[k][tx * 4 + j];
#pragma unroll
            for (int i = 0; i < 4; i++)
#pragma unroll
                for (int j = 0; j < 4; j++) acc[i][j] += ra[i] * rb[j];
        }
        __syncthreads();
    }
#pragma unroll
    for (int i = 0; i < 4; i++) {
        int row = bm + ty * 4 + i;
        float4 v = make_float4(acc[i][0], acc[i][1], acc[i][2], acc[i][3]);
        *reinterpret_cast<float4*>(&out[(size_t)row * DIM + bn + tx * 4]) = v;
    }
}

__device__ void structure_body(const int* __restrict__ nodes,
                               const int* __restrict__ edges, int nn) {
    __shared__ float deg[NEXP];
    __shared__ float edeg[MAXE];
    __shared__ int   Hc[NEXP][MAXE];
    __shared__ float P[NEXP][NEXP];
    __shared__ float u[NEXP];
    const int t = threadIdx.x;  // 256

    if (t < NEXP) deg[t] = 0.0f;
    if (t < MAXE) edeg[t] = 0.0f;
    for (int i = t; i < NEXP * MAXE; i += 256) (&Hc[0][0])[i] = 0;
    __syncthreads();

    int ne = nn / 2;
    if (ne > MAXE) ne = MAXE;
    for (int k = t; k < nn; k += 256) {
        int i = nodes[k], e = edges[k];
        if (i < 0 || i >= NEXP || e < 0 || e >= ne) continue;
        atomicAdd(&Hc[i][e], 1);
        atomicAdd(&deg[i], 1.0f);
        atomicAdd(&edeg[e], 1.0f);
    }
    __syncthreads();

    if (t < NEXP * NEXP) {
        int i = t >> 3, j = t & 7;
        float acc = 0.0f;
        for (int e = 0; e < ne; e++) {
            float binv = edeg[e] > 0.0f ? 1.0f / edeg[e] : 0.0f;
            acc += (float)Hc[i][e] * binv * (float)Hc[j][e];
        }
        float dinv = deg[i] > 0.0f ? 1.0f / deg[i] : 0.0f;
        P[i][j] = dinv * acc;
    }
    __syncthreads();
    if (t < NEXP) {
        float a = 0.0f;
        for (int i = 0; i < NEXP; i++) a += P[i][t];
        u[t] = a / (float)NEXP;
    }
    __syncthreads();
    if (t < NEXP) {
        float a = 0.0f;
        for (int i = 0; i < NEXP; i++) a += u[i] * P[i][t];
        g_v[t] = a;
    }
    if (t == 0) {
        float s = 0.0f;
        for (int i = 0; i < NEXP; i++) s += u[i];
        g_s = s;
    }
    __syncthreads();
}

__global__ __launch_bounds__(256, 4) void mega_kernel(
    const int* __restrict__ nodes, const int* __restrict__ edges, int nn,
    const float* __restrict__ W1, const float* __restrict__ W0,
    const float* __restrict__ Wc, const float* __restrict__ b0,
    const float* __restrict__ b1, const float* __restrict__ cb,
    const float* __restrict__ x) {
    const int bid = blockIdx.x;
    const int tid = threadIdx.x;

    if (bid >= FUS_BLOCKS) {
        if (tid == 0) {
            volatile int* f = (volatile int*)&g_bar[3];
            while (*f == 0) {}
        }
        __syncthreads();
        __threadfence();

        float v[NEXP];
#pragma unroll
        for (int e = 0; e < NEXP; e++) v[e] = __ldcg(&g_v[e]);

        const int rb = bid - FUS_BLOCKS;  // 0..127
        __nv_bfloat162* mh = reinterpret_cast<__nv_bfloat162*>(g_mh);
        __nv_bfloat162* ml = reinterpret_cast<__nv_bfloat162*>(g_ml);
#pragma unroll 1
        for (int it = 0; it < 32; it++) {
            int idx = rb * 8192 + it * 256 + tid;  // float4 index
            int n  = idx >> 7;
            int d4 = idx & 127;
            const float4* base =
                reinterpret_cast<const float4*>(x) + (size_t)n * NEXP * 128 + d4;
            float4 acc = make_float4(0.f, 0.f, 0.f, 0.f);
#pragma unroll
            for (int e = 0; e < NEXP; e++) {
                float4 q = base[(size_t)e * 128];
                acc.x += v[e] * q.x; acc.y += v[e] * q.y;
                acc.z += v[e] * q.z; acc.w += v[e] * q.w;
            }
            __nv_bfloat16 h0, h1, h2, h3, l0, l1, l2, l3;
            split_bf16(acc.x, h0, l0); split_bf16(acc.y, h1, l1);
            split_bf16(acc.z, h2, l2); split_bf16(acc.w, h3, l3);
            mh[idx * 2 + 0] = __halves2bfloat162(h0, h1);
            mh[idx * 2 + 1] = __halves2bfloat162(h2, h3);
            ml[idx * 2 + 0] = __halves2bfloat162(l0, l1);
            ml[idx * 2 + 1] = __halves2bfloat162(l2, l3);
        }
        return;
    }

    __shared__ float As[16][68];
    __shared__ float Bs[16][68];
    __shared__ float gred[8];
    const int z = bid >> 6, t6 = bid & 63;
    const int bm = (t6 >> 3) * 64, bn = (t6 & 7) * 64, kz = z * 128;

    if (bid == 0) {
        structure_body(nodes, edges, nn);
        if (tid == 0) {
            __threadfence();
            atomicExch(&g_bar[3], 1);
        }
    }

    if (bid < 256) {
        sk_compute(W1, W0, g_part + (size_t)z * DIM * DIM, bm, bn, kz, As, Bs);
    } else {
        int i = (bid - 256) * 256 + tid;
        if (i < TOKENS) { g_lnsum[i] = 0.0f; g_lnsq[i] = 0.0f; }
        if (i >= TOKENS && i < TOKENS + TOKENS / 64)
            g_lncnt[i - TOKENS] = 0;
    }

    gbar(0);

    if (bid < 64) {
        const float4* p = reinterpret_cast<const float4*>(g_part);
#pragma unroll
        for (int k = 0; k < 4; k++) {
            int i = bid * 1024 + k * 256 + tid;
            float4 s = make_float4(0.f, 0.f, 0.f, 0.f);
#pragma unroll
            for (int j = 0; j < NSPLIT; j++) {
                float4 a = p[i + j * 65536];
                s.x += a.x; s.y += a.y; s.z += a.z; s.w += a.w;
            }
            reinterpret_cast<float4*>(g_T1)[i] = s;
        }
    } else if (bid < 320) {
        const int half = tid >> 7, lt = tid & 127;
        const int r = (bid - 64) * 2 + half;
        float4 wv = reinterpret_cast<const float4*>(W1 + (size_t)r * DIM)[lt];
        float4 bv = reinterpret_cast<const float4*>(b0)[lt];
        float a = wv.x * bv.x + wv.y * bv.y + wv.z * bv.z + wv.w * bv.w;
        for (int o = 16; o; o >>= 1) a += __shfl_xor_sync(0xffffffffu, a, o);
        if ((tid & 31) == 0) gred[tid >> 5] = a;
        __syncthreads();
        if (lt == 0)
            g_tb[r] = gred[half * 4 + 0] + gred[half * 4 + 1] +
                      gred[half * 4 + 2] + gred[half * 4 + 3];
    }

    gbar(1);

    if (bid < 256)
        sk_compute(Wc, g_T1, g_part2 + (size_t)z * DIM * DIM, bm, bn, kz,
                   As, Bs);

    gbar(2);

    if (bid < 64) {
        const float4* p = reinterpret_cast<const float4*>(g_part2);
        __nv_bfloat162* wh = reinterpret_cast<__nv_bfloat162*>(g_wh);
        __nv_bfloat162* wl = reinterpret_cast<__nv_bfloat162*>(g_wl);
#pragma unroll
        for (int k = 0; k < 4; k++) {
            int i = bid * 1024 + k * 256 + tid;
            float4 s = make_float4(0.f, 0.f, 0.f, 0.f);
#pragma unroll
            for (int j = 0; j < NSPLIT; j++) {
                float4 a = p[i + j * 65536];
                s.x += a.x; s.y += a.y; s.z += a.z; s.w += a.w;
            }
            __nv_bfloat16 h0, h1, h2, h3, l0, l1, l2, l3;
            split_bf16(s.x, h0, l0); split_bf16(s.y, h1, l1);
            split_bf16(s.z, h2, l2); split_bf16(s.w, h3, l3);
            wh[i * 2 + 0] = __halves2bfloat162(h0, h1);
            wh[i * 2 + 1] = __halves2bfloat162(h2, h3);
            wl[i * 2 + 0] = __halves2bfloat162(l0, l1);
            wl[i * 2 + 1] = __halves2bfloat162(l2, l3);
        }
    } else if (bid < 320) {
        const int half = tid >> 7, lt = tid & 127;
        const int r = (bid - 64) * 2 + half;
        const float s = g_s;
        float4 wv = reinterpret_cast<const float4*>(Wc + (size_t)r * DIM)[lt];
        float4 bv = reinterpret_cast<const float4*>(b1)[lt];
        float a = wv.x * (s * g_tb[lt * 4 + 0] + bv.x) +
                  wv.y * (s * g_tb[lt * 4 + 1] + bv.y) +
                  wv.z * (s * g_tb[lt * 4 + 2] + bv.z) +
                  wv.w * (s * g_tb[lt * 4 + 3] + bv.w);
        for (int o = 16; o; o >>= 1) a += __shfl_xor_sync(0xffffffffu, a, o);
        __syncthreads();
        if ((tid & 31) == 0) gred[tid >> 5] = a;
        __syncthreads();
        if (lt == 0)
            g_bf[r] = gred[half * 4 + 0] + gred[half * 4 + 1] +
                      gred[half * 4 + 2] + gred[half * 4 + 3] + cb[r];
    }
}

// ---------------- fused HMMA GEMM + bias + GELU + cross-CTA LayerNorm -------
// Re-tiled: CTA 128(M)x128(N), grid (4,64); 8 warps as 4(M)x2(N), warp tile
// 32x64 (inner loop identical to R14). ldsm per k16-step: 20 -> 12.
// LN reduction across the 4 CTAs of a 128-row block (all 256 CTAs resident).
#define BK   32
#define BKP  40
#define A_T_E (128 * BKP)
#define B_T_E (128 * BKP)
#define OFF_AH 0
#define OFF_AL (A_T_E * 2)            // 10240
#define OFF_BH (2 * A_T_E * 2)        // 20480
#define OFF_BL (OFF_BH + B_T_E * 2)   // 30720
#define STG_B  (OFF_BL + B_T_E * 2)   // 40960 B per stage
#define GEMM_SMEM_B (2 * STG_B)       // 81920 B

__global__ __launch_bounds__(256, 2) void gemm_ln(
    const float* __restrict__ gamma, const float* __restrict__ beta,
    float* __restrict__ out) {
    extern __shared__ __nv_bfloat16 smem[];
    __shared__ float red[128][2][2];  // [row][n-warp][sum,sq]
    const uint32_t sb = smem_u32(smem);
    const int tid  = threadIdx.x;
    const int wid  = tid >> 5;
    const int lane = tid & 31;
    const int bm = blockIdx.y * 128;
    const int bn = blockIdx.x * 128;
    const int wm = (wid & 3) * 32;   // warp m offset (0,32,64,96)
    const int wn = (wid >> 2) * 64;  // warp n offset (0 or 64)

    // reset mega's spin barriers for the next replay
    if (blockIdx.x == 0 && blockIdx.y == 0 && tid < 4) g_bar[tid] = 0;

    float acc[2][8][4];
#pragma unroll
    for (int i = 0; i < 2; i++)
#pragma unroll
        for (int j = 0; j < 8; j++)
#pragma unroll
            for (int r = 0; r < 4; r++) acc[i][j][r] = 0.0f;

    const int lrow = (lane & 7) + ((lane >> 3) & 1) * 8;
    const int lcol = (lane >> 4) * 8;
    const uint32_t a_eoff = (uint32_t)(((wm + lrow) * BKP + lcol) * 2);
    const uint32_t b_eoff = (uint32_t)(((wn + lrow) * BKP + lcol) * 2);

    const int r_ld = tid >> 2;   // 0..63 (rows r_ld and r_ld+64)
    const int u_ld = tid & 3;

    // hoisted global source pointers (advance by BK per stage)
    const __nv_bfloat16* pA[2][2];  // [h/l][row half]
    const __nv_bfloat16* pBp[2][2];
    pA[0][0] = g_mh + (size_t)(bm + r_ld) * DIM + u_ld * 8;
    pA[0][1] = g_mh + (size_t)(bm + r_ld + 64) * DIM + u_ld * 8;
    pA[1][0] = g_ml + (size_t)(bm + r_ld) * DIM + u_ld * 8;
    pA[1][1] = g_ml + (size_t)(bm + r_ld + 64) * DIM + u_ld * 8;
    pBp[0][0] = g_wh + (size_t)(bn + r_ld) * DIM + u_ld * 8;
    pBp[0][1] = g_wh + (size_t)(bn + r_ld + 64) * DIM + u_ld * 8;
    pBp[1][0] = g_wl + (size_t)(bn + r_ld) * DIM + u_ld * 8;
    pBp[1][1] = g_wl + (size_t)(bn + r_ld + 64) * DIM + u_ld * 8;

    const uint32_t doff0 = (uint32_t)((r_ld * BKP + u_ld * 8) * 2);
    const uint32_t doff1 = (uint32_t)(((r_ld + 64) * BKP + u_ld * 8) * 2);

    uint32_t sAh[2], sAl[2], sBh[2], sBl[2];
#pragma unroll
    for (int b = 0; b < 2; b++) {
        const uint32_t stg = sb + (uint32_t)(b * STG_B);
        sAh[b] = stg + OFF_AH + a_eoff;
        sAl[b] = stg + OFF_AL + a_eoff;
        sBh[b] = stg + OFF_BH + b_eoff;
        sBl[b] = stg + OFF_BL + b_eoff;
    }

    auto issue_stage = [&](int buf) {
        const uint32_t stg = sb + (uint32_t)(buf * STG_B);
        cp_async16(stg + OFF_AH + doff0, pA[0][0]);
        cp_async16(stg + OFF_AH + doff1, pA[0][1]);
        cp_async16(stg + OFF_AL + doff0, pA[1][0]);
        cp_async16(stg + OFF_AL + doff1, pA[1][1]);
        cp_async16(stg + OFF_BH + doff0, pBp[0][0]);
        cp_async16(stg + OFF_BH + doff1, pBp[0][1]);
        cp_async16(stg + OFF_BL + doff0, pBp[1][0]);
        cp_async16(stg + OFF_BL + doff1, pBp[1][1]);
#pragma unroll
        for (int i = 0; i < 2; i++)
#pragma unroll
            for (int j = 0; j < 2; j++) { pA[i][j] += BK; pBp[i][j] += BK; }
    };

    issue_stage(0);
    cp_commit();

    const int NSTG = DIM / BK;  // 16
    for (int c = 0; c < NSTG; c++) {
        const int buf = c & 1;
        if (c + 1 < NSTG) { issue_stage((c + 1) & 1); cp_commit(); }
        if (c + 1 < NSTG) cp_wait<1>(); else cp_wait<0>();
        __syncthreads();

        const uint32_t pAhS = sAh[buf];
        const uint32_t pAlS = sAl[buf];
        const uint32_t pBhS = sBh[buf];
        const uint32_t pBlS = sBl[buf];

#pragma unroll
        for (int kk = 0; kk < BK; kk += 16) {
            const uint32_t ko = (uint32_t)(kk * 2);
            uint32_t Ahf[2][4], Alf[2][4];
#pragma unroll
            for (int mi = 0; mi < 2; mi++) {
                const uint32_t o = (uint32_t)(mi * 16 * BKP * 2) + ko;
                ldsm_x4(Ahf[mi], pAhS + o);
                ldsm_x4(Alf[mi], pAlS + o);
            }
            uint32_t Bh[2][4], Bl[2][4];
            ldsm_x4(Bh[0], pBhS + ko);
            ldsm_x4(Bl[0], pBlS + ko);
#pragma unroll
            for (int g = 0; g < 4; g++) {
                const int cur = g & 1;
                if (g < 3) {
                    const uint32_t o = (uint32_t)((g + 1) * 16 * BKP * 2) + ko;
                    ldsm_x4(Bh[cur ^ 1], pBhS + o);
                    ldsm_x4(Bl[cur ^ 1], pBlS + o);
                }
#pragma unroll
                for (int hf = 0; hf < 2; hf++) {
                    const int n8 = g * 2 + hf;
                    const uint32_t bh0 = Bh[cur][hf], bh1 = Bh[cur][hf + 2];
                    const uint32_t bl0 = Bl[cur][hf], bl1 = Bl[cur][hf + 2];
#pragma unroll
                    for (int mi = 0; mi < 2; mi++) {
                        mma_bf16(acc[mi][n8], Ahf[mi], bh0, bh1);
                        mma_bf16(acc[mi][n8], Ahf[mi], bl0, bl1);
                        mma_bf16(acc[mi][n8], Alf[mi], bh0, bh1);
                    }
                }
            }
        }
        __syncthreads();
    }

    // ---------------- epilogue: bias + GELU + cross-CTA LayerNorm -----------
    const int q = lane >> 2;
    float sm_[2][2] = {{0.f, 0.f}, {0.f, 0.f}};
    float sq_[2][2] = {{0.f, 0.f}, {0.f, 0.f}};
#pragma unroll
    for (int mi = 0; mi < 2; mi++)
#pragma unroll
        for (int n8 = 0; n8 < 8; n8++) {
            const int col = bn + wn + n8 * 8 + (lane & 3) * 2;
            const float2 bv = *reinterpret_cast<const float2*>(&g_bf[col]);
            float g0 = gelu_exact(acc[mi][n8][0] + bv.x);
            float g1 = gelu_exact(acc[mi][n8][1] + bv.y);
            float g2 = gelu_exact(acc[mi][n8][2] + bv.x);
            float g3 = gelu_exact(acc[mi][n8][3] + bv.y);
            acc[mi][n8][0] = g0; acc[mi][n8][1] = g1;
            acc[mi][n8][2] = g2; acc[mi][n8][3] = g3;
            sm_[mi][0] += g0 + g1; sq_[mi][0] += g0 * g0 + g1 * g1;
            sm_[mi][1] += g2 + g3; sq_[mi][1] += g2 * g2 + g3 * g3;
        }
#pragma unroll
    for (int o = 1; o <= 2; o <<= 1) {
#pragma unroll
        for (int mi = 0; mi < 2; mi++)
#pragma unroll
            for (int h = 0; h < 2; h++) {
                sm_[mi][h] += __shfl_xor_sync(0xffffffffu, sm_[mi][h], o);
                sq_[mi][h] += __shfl_xor_sync(0xffffffffu, sq_[mi][h], o);
            }
    }
    const int nw = wid >> 2;  // n-warp index (0 or 1)
    if ((lane & 3) == 0) {
#pragma unroll
        for (int mi = 0; mi < 2; mi++)
#pragma unroll
            for (int h = 0; h < 2; h++) {
                red[wm + mi * 16 + q + h * 8][nw][0] = sm_[mi][h];
                red[wm + mi * 16 + q + h * 8][nw][1] = sq_[mi][h];
            }
    }
    __syncthreads();

    // per-row partials -> global atomics (threads 0..127 own one row each)
    if (tid < 128) {
        float s  = red[tid][0][0] + red[tid][1][0];
        float qq = red[tid][0][1] + red[tid][1][1];
        atomicAdd(&g_lnsum[bm + tid], s);
        atomicAdd(&g_lnsq[bm + tid], qq);
        __threadfence();
    }
    __syncthreads();
    if (tid == 0) {
        atomicAdd(&g_lncnt[blockIdx.y], 1);
        volatile int* cnt = (volatile int*)&g_lncnt[blockIdx.y];
        while (*cnt < 4) {}
    }
    __syncthreads();
    __threadfence();

    const float inv_d = 1.0f / (float)DIM;
    float mu[2][2], iv[2][2];
#pragma unroll
    for (int mi = 0; mi < 2; mi++)
#pragma unroll
        for (int h = 0; h < 2; h++) {
            const int row = bm + wm + mi * 16 + q + h * 8;
            float s  = __ldcg(&g_lnsum[row]);
            float qq = __ldcg(&g_lnsq[row]);
            float m = s * inv_d;
            mu[mi][h] = m;
            iv[mi][h] = rsqrtf(qq * inv_d - m * m + LN_EPS);
        }

#pragma unroll
    for (int mi = 0; mi < 2; mi++) {
        const int r0 = bm + wm + mi * 16 + q;
        const int r1 = r0 + 8;
#pragma unroll
        for (int n8 = 0; n8 < 8; n8++) {
            const int col = bn + wn + n8 * 8 + (lane & 3) * 2;
            const float2 ga = *reinterpret_cast<const float2*>(&gamma[col]);
            const float2 be = *reinterpret_cast<const float2*>(&beta[col]);
            float2 o0, o1;
            o0.x = (acc[mi][n8][0] - mu[mi][0]) * iv[mi][0] * ga.x + be.x;
            o0.y = (acc[mi][n8][1] - mu[mi][0]) * iv[mi][0] * ga.y + be.y;
            o1.x = (acc[mi][n8][2] - mu[mi][1]) * iv[mi][1] * ga.x + be.x;
            o1.y = (acc[mi][n8][3] - mu[mi][1]) * iv[mi][1] * ga.y + be.y;
            *reinterpret_cast<float2*>(&out[(size_t)r0 * DIM + col]) = o0;
            *reinterpret_cast<float2*>(&out[(size_t)r1 * DIM + col]) = o1;
        }
    }
}

// ---------------- launcher ---------------------------------------------------
extern "C" void kernel_launch(void* const* d_in, const int* in_sizes, int n_in,
                              void* d_out, int out_size) {
    const float* x     = (const float*)d_in[0];
    const float* hw    = (const float*)d_in[1];
    const float* hb    = (const float*)d_in[2];
    const float* cw    = (const float*)d_in[3];
    const float* cbias = (const float*)d_in[4];
    const float* lg    = (const float*)d_in[5];
    const float* lb    = (const float*)d_in[6];
    const int*   nodes = (const int*)d_in[7];
    const int*   edges = (const int*)d_in[8];
    const int    nn    = in_sizes[7];
    float*       out   = (float*)d_out;

    const float* W0 = hw;
    const float* W1 = hw + DIM * DIM;
    const float* b0 = hb;
    const float* b1 = hb + DIM;

    cudaFuncSetAttribute(gemm_ln, cudaFuncAttributeMaxDynamicSharedMemorySize,
                         GEMM_SMEM_B);

    // 1) mega: fusion chain (blocks 0-383, also zeroes LN buffers)
    //          || expert reduce (blocks 384-511)
    mega_kernel<<<MEGA_BLOCKS, 256>>>(nodes, edges, nn, W1, W0, cw, b0, b1,
                                      cbias, x);

    // 2) main HMMA GEMM + bias + GELU + cross-CTA LayerNorm -> out
    //    (also zeroes g_bar for the next replay's mega)
    {
        dim3 grid(4, TOKENS / 128);
        gemm_ln<<<grid, 256, GEMM_SMEM_B>>>(lg, lb, out);
    }
}